// round 2
// baseline (speedup 1.0000x reference)
#include <cuda_runtime.h>
#include <math.h>

#define Bn     1024
#define Ln     64
#define Hn     512
#define DEPTHn 4

// Ping-pong RNN state: g_S[parity][layer][batch][hidden]
__device__ float g_S[2][DEPTHn][Bn][Hn];
// History of layer-3 outputs for the final log-prob pass
__device__ float g_hist[Ln][Bn][Hn];

// ---------------------------------------------------------------------------
// Zero the parity-0 state (initial carry) every launch (determinism).
// ---------------------------------------------------------------------------
__global__ void zero_state_kernel() {
    int i = blockIdx.x * blockDim.x + threadIdx.x;   // 2048*256 = 524288 float4s
    float4* p = reinterpret_cast<float4*>(&g_S[0][0][0][0]);
    p[i] = make_float4(0.f, 0.f, 0.f, 0.f);
}

// ---------------------------------------------------------------------------
// Fused RNN layer GEMM:
//   C = elu( S_j(old) @ W1  [+ h_{j-1}(new) @ W2]  + bias  [+ Win0[x_prev] row] )
// M=1024 (batch), N=512 (hidden out), K=512 per phase.
// Tile 64x64, BK=16, 256 threads, 4x4 micro-tile, float4 smem reads.
// ---------------------------------------------------------------------------
template <bool DUAL, bool LAYER0, bool STORE_HIST>
__global__ void __launch_bounds__(256) layer_kernel(
    const float* __restrict__ W1,    // Wc_j   [H][H] (k-major rows)
    const float* __restrict__ W2,    // Win_j  [H][H] (DUAL only)
    const float* __restrict__ bias,  // bc_j   [H]
    const int*   __restrict__ xsym,  // [B][L]
    const float* __restrict__ Win0,  // [2][H]
    int t, int pin, int j)
{
    const int pout = pin ^ 1;
    const float* A1 = &g_S[pin][j][0][0];                       // old state
    const float* A2 = DUAL ? &g_S[pout][j - 1][0][0] : nullptr; // this-step h_{j-1}
    float* C = &g_S[pout][j][0][0];

    __shared__ __align__(16) float As[16][68];  // [k][m], +4 pad keeps float4 align & banks clean
    __shared__ __align__(16) float Ws[16][68];  // [k][n]

    const int tid = threadIdx.x;
    const int tx = tid & 15;     // -> n micro-tile
    const int ty = tid >> 4;     // -> m micro-tile
    const int m0 = blockIdx.y * 64;
    const int n0 = blockIdx.x * 64;

    // load-index mapping
    const int ak = tid & 15;     // k within chunk (coalesced along k)
    const int ar = tid >> 4;     // row 0..15 (+16 per pass)
    const int wn = tid & 63;     // n (coalesced)
    const int wk = tid >> 6;     // k row 0..3 (+4 per pass)

    float acc[4][4];
#pragma unroll
    for (int i = 0; i < 4; i++)
#pragma unroll
        for (int jj = 0; jj < 4; jj++) acc[i][jj] = 0.f;

    const int nPhases = DUAL ? 2 : 1;
    for (int ph = 0; ph < nPhases; ph++) {
        const float* A = (ph == 0) ? A1 : A2;
        const float* W = (ph == 0) ? W1 : W2;
        for (int kc = 0; kc < Hn; kc += 16) {
            __syncthreads();
#pragma unroll
            for (int p = 0; p < 4; p++) {
                As[ak][ar + p * 16]      = A[(m0 + ar + p * 16) * Hn + kc + ak];
                Ws[wk + p * 4][wn]       = W[(kc + wk + p * 4) * Hn + n0 + wn];
            }
            __syncthreads();
#pragma unroll
            for (int kk = 0; kk < 16; kk++) {
                float4 a4 = *reinterpret_cast<const float4*>(&As[kk][ty * 4]);
                float4 w4 = *reinterpret_cast<const float4*>(&Ws[kk][tx * 4]);
                float av[4] = {a4.x, a4.y, a4.z, a4.w};
                float wv[4] = {w4.x, w4.y, w4.z, w4.w};
#pragma unroll
                for (int i = 0; i < 4; i++)
#pragma unroll
                    for (int jj = 0; jj < 4; jj++)
                        acc[i][jj] += av[i] * wv[jj];
            }
        }
    }

    // epilogue: bias (+ one-hot Win0 row for layer 0), elu, store (+ history)
    float bv[4];
#pragma unroll
    for (int jj = 0; jj < 4; jj++) bv[jj] = bias[n0 + tx * 4 + jj];

#pragma unroll
    for (int i = 0; i < 4; i++) {
        const int m = m0 + ty * 4 + i;
        float add0[4] = {0.f, 0.f, 0.f, 0.f};
        if (LAYER0) {
            if (t > 0) {
                const int idx = xsym[m * Ln + (t - 1)];
                float4 wr = *reinterpret_cast<const float4*>(&Win0[idx * Hn + n0 + tx * 4]);
                add0[0] = wr.x; add0[1] = wr.y; add0[2] = wr.z; add0[3] = wr.w;
            }
        }
        float v[4];
#pragma unroll
        for (int jj = 0; jj < 4; jj++) {
            float val = acc[i][jj] + bv[jj] + add0[jj];
            v[jj] = (val > 0.f) ? val : expm1f(val);   // elu, alpha=1
        }
        float4 o = make_float4(v[0], v[1], v[2], v[3]);
        *reinterpret_cast<float4*>(&C[m * Hn + n0 + tx * 4]) = o;
        if (STORE_HIST)
            *reinterpret_cast<float4*>(&g_hist[t][m][n0 + tx * 4]) = o;
    }
}

// ---------------------------------------------------------------------------
// Final pass: one warp per batch row.
//   logits[t] = h3[t,b,:] @ Wout + bout ; lp += logits[x[b,t]] - logsumexp
//   out[b] = 0.5 * sum_t lp
// ---------------------------------------------------------------------------
__global__ void logp_kernel(const float* __restrict__ Wout,  // [H][2]
                            const float* __restrict__ bout,  // [2]
                            const int*   __restrict__ xsym,  // [B][L]
                            float* __restrict__ out)         // [B]
{
    const int gw   = (blockIdx.x * blockDim.x + threadIdx.x) >> 5;
    const int lane = threadIdx.x & 31;
    if (gw >= Bn) return;
    const int b = gw;

    float w0[16], w1[16];
#pragma unroll
    for (int i = 0; i < 16; i++) {
        const int k = lane + 32 * i;
        w0[i] = Wout[k * 2 + 0];
        w1[i] = Wout[k * 2 + 1];
    }
    const float b0 = bout[0], b1 = bout[1];

    float acc = 0.f;
    for (int t = 0; t < Ln; t++) {
        const float* h = &g_hist[t][b][0];
        float s0 = 0.f, s1 = 0.f;
#pragma unroll
        for (int i = 0; i < 16; i++) {
            const float hv = h[lane + 32 * i];
            s0 += hv * w0[i];
            s1 += hv * w1[i];
        }
#pragma unroll
        for (int off = 16; off > 0; off >>= 1) {
            s0 += __shfl_xor_sync(0xffffffffu, s0, off);
            s1 += __shfl_xor_sync(0xffffffffu, s1, off);
        }
        s0 += b0; s1 += b1;
        const float m   = fmaxf(s0, s1);
        const float lse = m + logf(expf(s0 - m) + expf(s1 - m));
        const float sel = (xsym[b * Ln + t] == 0) ? s0 : s1;
        acc += sel - lse;
    }
    if (lane == 0) out[b] = 0.5f * acc;
}

// ---------------------------------------------------------------------------
extern "C" void kernel_launch(void* const* d_in, const int* in_sizes, int n_in,
                              void* d_out, int out_size) {
    (void)in_sizes; (void)n_in; (void)out_size;
    const int*   x        = (const int*)  d_in[0];  // [B, L] int32
    const float* Win0     = (const float*)d_in[1];  // [2, H]
    const float* Win_rest = (const float*)d_in[2];  // [3, H, H]
    const float* Wc       = (const float*)d_in[3];  // [4, H, H]
    const float* bc       = (const float*)d_in[4];  // [4, H]
    const float* Wout     = (const float*)d_in[5];  // [H, 2]
    const float* bout     = (const float*)d_in[6];  // [2]
    float* out = (float*)d_out;                     // [B]

    zero_state_kernel<<<2048, 256>>>();

    const dim3 grid(Hn / 64, Bn / 64);  // (8, 16) = 128 CTAs
    for (int t = 0; t < Ln; t++) {
        const int pin = t & 1;
        // layer 0: single GEMM (K=512) + one-hot Win0 gather
        layer_kernel<false, true, false><<<grid, 256>>>(
            Wc + 0 * Hn * Hn, nullptr, bc + 0 * Hn, x, Win0, t, pin, 0);
        // layers 1..2: dual GEMM (K=1024)
        layer_kernel<true, false, false><<<grid, 256>>>(
            Wc + 1 * Hn * Hn, Win_rest + 0 * Hn * Hn, bc + 1 * Hn, x, Win0, t, pin, 1);
        layer_kernel<true, false, false><<<grid, 256>>>(
            Wc + 2 * Hn * Hn, Win_rest + 1 * Hn * Hn, bc + 2 * Hn, x, Win0, t, pin, 2);
        // layer 3: dual GEMM + history store
        layer_kernel<true, false, true><<<grid, 256>>>(
            Wc + 3 * Hn * Hn, Win_rest + 2 * Hn * Hn, bc + 3 * Hn, x, Win0, t, pin, 3);
    }

    logp_kernel<<<Bn / 8, 256>>>(Wout, bout, x, out);
}

// round 3
// speedup vs baseline: 2.4132x; 2.4132x over previous
#include <cuda_runtime.h>
#include <math.h>

#define Bn   1024
#define Ln   64
#define Hn   512
#define NCTA 128
#define BM   64
#define BN   64
#define BK   32
#define NTHREADS 256

// Ping-pong RNN state + history
__device__ float g_S[2][4][Bn][Hn];
__device__ float g_hist[Ln][Bn][Hn];
// Global software barrier state
__device__ unsigned g_count;
__device__ volatile unsigned g_gen;

__device__ __forceinline__ unsigned f2tf32(float x) {
    unsigned u;
    asm("cvt.rna.tf32.f32 %0, %1;" : "=r"(u) : "f"(x));
    return u;
}

__device__ __forceinline__ void mma8(float c[4], const unsigned a[4], const unsigned b[2]) {
    asm volatile(
        "mma.sync.aligned.m16n8k8.row.col.f32.tf32.tf32.f32 "
        "{%0,%1,%2,%3}, {%4,%5,%6,%7}, {%8,%9}, {%0,%1,%2,%3};"
        : "+f"(c[0]), "+f"(c[1]), "+f"(c[2]), "+f"(c[3])
        : "r"(a[0]), "r"(a[1]), "r"(a[2]), "r"(a[3]), "r"(b[0]), "r"(b[1]));
}

// Global barrier: all 128 CTAs are co-resident (1 CTA/SM, grid < SM count).
__device__ __forceinline__ void gbar(unsigned target) {
    __syncthreads();
    if (threadIdx.x == 0) {
        __threadfence();                      // publish my writes (and flush L1)
        unsigned t = atomicAdd(&g_count, 1);
        if (t == NCTA - 1) {
            atomicExch(&g_count, 0);
            __threadfence();
            g_gen = target;                   // release
        } else {
            while ((int)(g_gen - target) < 0) {}
            __threadfence();
        }
    }
    __syncthreads();
}

__global__ void __launch_bounds__(NTHREADS, 1) rnn_persistent(
    const int*   __restrict__ x,         // [B][L]
    const float* __restrict__ Win0,      // [2][H]
    const float* __restrict__ Win_rest,  // [3][H][H]
    const float* __restrict__ Wc,        // [4][H][H]
    const float* __restrict__ bc)        // [4][H]
{
    __shared__ unsigned As[2][BM][BK + 4];  // row stride 36 words (144B, 16B-aligned)
    __shared__ unsigned Bs[2][BK][BN + 8];  // row stride 72 words (288B)

    const int tid  = threadIdx.x;
    const int cta  = blockIdx.x;
    const int m0   = (cta >> 3) * BM;       // 16 m-tiles
    const int n0   = (cta & 7)  * BN;       // 8 n-tiles

    const int warp = tid >> 5, lane = tid & 31;
    const int mw   = warp & 1;              // 2 warps along m
    const int nw   = warp >> 1;             // 4 warps along n
    const int quad = lane >> 2, qt = lane & 3;

    // staging index mapping (float4 loads)
    const int ar  = tid >> 3;               // 0..31 (A rows ar, ar+32)
    const int ak4 = (tid & 7) * 4;          // k offset
    const int wk  = tid >> 4;               // 0..15 (W k-rows wk, wk+16)
    const int wn4 = (tid & 15) * 4;         // n offset

    unsigned base = g_gen;                  // stable until first barrier releases
    unsigned bar  = 0;

    // Zero the initial carry S[0][*] (this CTA's tile slice), every launch.
    const float4 z4 = make_float4(0.f, 0.f, 0.f, 0.f);
    for (int i = tid; i < 4 * 64 * 16; i += NTHREADS) {
        int j = i >> 10;
        int r = (i >> 4) & 63;
        int c = i & 15;
        *reinterpret_cast<float4*>(&g_S[0][j][m0 + r][n0 + c * 4]) = z4;
    }
    gbar(base + (++bar));

    for (int t = 0; t < Ln; t++) {
        const int pin = t & 1, pout = pin ^ 1;
        for (int j = 0; j < 4; j++) {
            const float* A1 = &g_S[pin][j][0][0];                            // old state, K=512
            const float* A2 = (j > 0) ? &g_S[pout][j - 1][0][0] : A1;        // fresh h_{j-1}
            const float* W1 = Wc + j * Hn * Hn;
            const float* W2 = (j > 0) ? (Win_rest + (j - 1) * Hn * Hn) : W1;
            const int nChunks = (j > 0) ? 32 : 16;                           // BK=32 chunks

            float acc[2][2][4];
#pragma unroll
            for (int a = 0; a < 2; a++)
#pragma unroll
                for (int b = 0; b < 2; b++)
#pragma unroll
                    for (int v = 0; v < 4; v++) acc[a][b][v] = 0.f;

            // ---- prologue: stage chunk 0 ----
            {
                const float4 va0 = *reinterpret_cast<const float4*>(&A1[(m0 + ar) * Hn + ak4]);
                const float4 va1 = *reinterpret_cast<const float4*>(&A1[(m0 + ar + 32) * Hn + ak4]);
                const float4 vw0 = *reinterpret_cast<const float4*>(&W1[wk * Hn + n0 + wn4]);
                const float4 vw1 = *reinterpret_cast<const float4*>(&W1[(wk + 16) * Hn + n0 + wn4]);
                uint4 u;
                u.x = f2tf32(va0.x); u.y = f2tf32(va0.y); u.z = f2tf32(va0.z); u.w = f2tf32(va0.w);
                *reinterpret_cast<uint4*>(&As[0][ar][ak4]) = u;
                u.x = f2tf32(va1.x); u.y = f2tf32(va1.y); u.z = f2tf32(va1.z); u.w = f2tf32(va1.w);
                *reinterpret_cast<uint4*>(&As[0][ar + 32][ak4]) = u;
                u.x = f2tf32(vw0.x); u.y = f2tf32(vw0.y); u.z = f2tf32(vw0.z); u.w = f2tf32(vw0.w);
                *reinterpret_cast<uint4*>(&Bs[0][wk][wn4]) = u;
                u.x = f2tf32(vw1.x); u.y = f2tf32(vw1.y); u.z = f2tf32(vw1.z); u.w = f2tf32(vw1.w);
                *reinterpret_cast<uint4*>(&Bs[0][wk + 16][wn4]) = u;
            }
            __syncthreads();

            int buf = 0;
            for (int cc = 0; cc < nChunks; cc++) {
                // prefetch next chunk into registers
                float4 na0, na1, nw0v, nw1v;
                const bool more = (cc + 1 < nChunks);
                if (more) {
                    const int ph = (cc + 1) >> 4;          // phase 0: K of S@Wc, phase 1: h@Win
                    const float* Ap = ph ? A2 : A1;
                    const float* Wp = ph ? W2 : W1;
                    const int kc = ((cc + 1) & 15) * BK;
                    na0  = *reinterpret_cast<const float4*>(&Ap[(m0 + ar) * Hn + kc + ak4]);
                    na1  = *reinterpret_cast<const float4*>(&Ap[(m0 + ar + 32) * Hn + kc + ak4]);
                    nw0v = *reinterpret_cast<const float4*>(&Wp[(kc + wk) * Hn + n0 + wn4]);
                    nw1v = *reinterpret_cast<const float4*>(&Wp[(kc + wk + 16) * Hn + n0 + wn4]);
                }

                // compute current buffer: 4 k8-steps
#pragma unroll
                for (int k8 = 0; k8 < BK; k8 += 8) {
                    unsigned af[2][4], bf[2][2];
#pragma unroll
                    for (int ma = 0; ma < 2; ma++) {
                        const int arow = mw * 32 + ma * 16;
                        af[ma][0] = As[buf][arow + quad][k8 + qt];
                        af[ma][1] = As[buf][arow + quad + 8][k8 + qt];
                        af[ma][2] = As[buf][arow + quad][k8 + qt + 4];
                        af[ma][3] = As[buf][arow + quad + 8][k8 + qt + 4];
                    }
#pragma unroll
                    for (int na = 0; na < 2; na++) {
                        const int bcol = nw * 16 + na * 8;
                        bf[na][0] = Bs[buf][k8 + qt][bcol + quad];
                        bf[na][1] = Bs[buf][k8 + qt + 4][bcol + quad];
                    }
#pragma unroll
                    for (int ma = 0; ma < 2; ma++)
#pragma unroll
                        for (int na = 0; na < 2; na++)
                            mma8(acc[ma][na], af[ma], bf[na]);
                }

                // stage next chunk into the other buffer
                if (more) {
                    const int nb = buf ^ 1;
                    uint4 u;
                    u.x = f2tf32(na0.x); u.y = f2tf32(na0.y); u.z = f2tf32(na0.z); u.w = f2tf32(na0.w);
                    *reinterpret_cast<uint4*>(&As[nb][ar][ak4]) = u;
                    u.x = f2tf32(na1.x); u.y = f2tf32(na1.y); u.z = f2tf32(na1.z); u.w = f2tf32(na1.w);
                    *reinterpret_cast<uint4*>(&As[nb][ar + 32][ak4]) = u;
                    u.x = f2tf32(nw0v.x); u.y = f2tf32(nw0v.y); u.z = f2tf32(nw0v.z); u.w = f2tf32(nw0v.w);
                    *reinterpret_cast<uint4*>(&Bs[nb][wk][wn4]) = u;
                    u.x = f2tf32(nw1v.x); u.y = f2tf32(nw1v.y); u.z = f2tf32(nw1v.z); u.w = f2tf32(nw1v.w);
                    *reinterpret_cast<uint4*>(&Bs[nb][wk + 16][wn4]) = u;
                }
                __syncthreads();
                buf ^= 1;
            }

            // ---- epilogue: bias (+ Win0 one-hot row for layer 0), ELU, store ----
#pragma unroll
            for (int ma = 0; ma < 2; ma++) {
                const int row0 = m0 + mw * 32 + ma * 16 + quad;   // rows row0, row0+8
                int idx0 = 0, idx1 = 0;
                const bool l0add = (j == 0) && (t > 0);
                if (l0add) {
                    idx0 = x[row0 * Ln + (t - 1)];
                    idx1 = x[(row0 + 8) * Ln + (t - 1)];
                }
#pragma unroll
                for (int na = 0; na < 2; na++) {
                    const int col = n0 + nw * 16 + na * 8 + 2 * qt;
                    const float2 bv = *reinterpret_cast<const float2*>(&bc[j * Hn + col]);
                    float2 w0 = make_float2(0.f, 0.f), w1 = make_float2(0.f, 0.f);
                    if (l0add) {
                        w0 = *reinterpret_cast<const float2*>(&Win0[idx0 * Hn + col]);
                        w1 = *reinterpret_cast<const float2*>(&Win0[idx1 * Hn + col]);
                    }
                    float v0 = acc[ma][na][0] + bv.x + w0.x;
                    float v1 = acc[ma][na][1] + bv.y + w0.y;
                    float v2 = acc[ma][na][2] + bv.x + w1.x;
                    float v3 = acc[ma][na][3] + bv.y + w1.y;
                    v0 = (v0 > 0.f) ? v0 : expm1f(v0);
                    v1 = (v1 > 0.f) ? v1 : expm1f(v1);
                    v2 = (v2 > 0.f) ? v2 : expm1f(v2);
                    v3 = (v3 > 0.f) ? v3 : expm1f(v3);
                    *reinterpret_cast<float2*>(&g_S[pout][j][row0][col])     = make_float2(v0, v1);
                    *reinterpret_cast<float2*>(&g_S[pout][j][row0 + 8][col]) = make_float2(v2, v3);
                    if (j == 3) {
                        *reinterpret_cast<float2*>(&g_hist[t][row0][col])     = make_float2(v0, v1);
                        *reinterpret_cast<float2*>(&g_hist[t][row0 + 8][col]) = make_float2(v2, v3);
                    }
                }
            }

            gbar(base + (++bar));
        }
    }
}

// ---------------------------------------------------------------------------
// Final pass: one warp per batch row (verified correct in round 2).
// ---------------------------------------------------------------------------
__global__ void logp_kernel(const float* __restrict__ Wout,  // [H][2]
                            const float* __restrict__ bout,  // [2]
                            const int*   __restrict__ xsym,  // [B][L]
                            float* __restrict__ out)         // [B]
{
    const int gw   = (blockIdx.x * blockDim.x + threadIdx.x) >> 5;
    const int lane = threadIdx.x & 31;
    if (gw >= Bn) return;
    const int b = gw;

    float w0[16], w1[16];
#pragma unroll
    for (int i = 0; i < 16; i++) {
        const int k = lane + 32 * i;
        w0[i] = Wout[k * 2 + 0];
        w1[i] = Wout[k * 2 + 1];
    }
    const float b0 = bout[0], b1 = bout[1];

    float acc = 0.f;
    for (int t = 0; t < Ln; t++) {
        const float* h = &g_hist[t][b][0];
        float s0 = 0.f, s1 = 0.f;
#pragma unroll
        for (int i = 0; i < 16; i++) {
            const float hv = h[lane + 32 * i];
            s0 += hv * w0[i];
            s1 += hv * w1[i];
        }
#pragma unroll
        for (int off = 16; off > 0; off >>= 1) {
            s0 += __shfl_xor_sync(0xffffffffu, s0, off);
            s1 += __shfl_xor_sync(0xffffffffu, s1, off);
        }
        s0 += b0; s1 += b1;
        const float m   = fmaxf(s0, s1);
        const float lse = m + logf(expf(s0 - m) + expf(s1 - m));
        const float sel = (xsym[b * Ln + t] == 0) ? s0 : s1;
        acc += sel - lse;
    }
    if (lane == 0) out[b] = 0.5f * acc;
}

// ---------------------------------------------------------------------------
extern "C" void kernel_launch(void* const* d_in, const int* in_sizes, int n_in,
                              void* d_out, int out_size) {
    (void)in_sizes; (void)n_in; (void)out_size;
    const int*   x        = (const int*)  d_in[0];  // [B, L]
    const float* Win0     = (const float*)d_in[1];  // [2, H]
    const float* Win_rest = (const float*)d_in[2];  // [3, H, H]
    const float* Wc       = (const float*)d_in[3];  // [4, H, H]
    const float* bc       = (const float*)d_in[4];  // [4, H]
    const float* Wout     = (const float*)d_in[5];  // [H, 2]
    const float* bout     = (const float*)d_in[6];  // [2]
    float* out = (float*)d_out;                     // [B]

    rnn_persistent<<<NCTA, NTHREADS>>>(x, Win0, Win_rest, Wc, bc);
    logp_kernel<<<Bn / 8, 256>>>(Wout, bout, x, out);
}

// round 5
// speedup vs baseline: 2.8829x; 1.1946x over previous
#include <cuda_runtime.h>
#include <cuda_bf16.h>
#include <math.h>

#define Bn 1024
#define Ln 64
#define Hn 512
#define NCTA 128
#define NTHREADS 256

// fp32 state/weights holding tf32-rounded values; fp32 history.
__device__ float g_S[2][4][Bn][Hn];     // 16 MB ping-pong state
__device__ float g_W[7][Hn][Hn];        // [0..3]=Wc, [4..6]=Win_rest (tf32-rounded)
__device__ float g_hist[Ln][Bn][Hn];    // 128 MB layer-3 outputs (full fp32)
__device__ unsigned g_count;
__device__ volatile unsigned g_gen;

// smem geometry (dynamic): A[2][128][36] floats + B[2][32][136] floats
#define APITCH 36
#define BPITCH 136
#define A_WORDS (2 * 128 * APITCH)      // 9216
#define B_WORDS (2 * 32 * BPITCH)       // 8704
#define SMEM_BYTES ((A_WORDS + B_WORDS) * 4)  // 71680

// ---------------------------------------------------------------------------
__device__ __forceinline__ unsigned f2tf32(float x) {
    unsigned u;
    asm("cvt.rna.tf32.f32 %0, %1;" : "=r"(u) : "f"(x));
    return u;
}
__device__ __forceinline__ float tf32r(float x) { return __uint_as_float(f2tf32(x)); }

__device__ __forceinline__ void cp16(void* dst, const void* src) {
    unsigned d = (unsigned)__cvta_generic_to_shared(dst);
    asm volatile("cp.async.cg.shared.global [%0], [%1], 16;" :: "r"(d), "l"(src));
}
__device__ __forceinline__ void cp_commit() {
    asm volatile("cp.async.commit_group;" ::: "memory");
}
__device__ __forceinline__ void cp_wait0() {
    asm volatile("cp.async.wait_group 0;" ::: "memory");
}
__device__ __forceinline__ void mma8(float c[4], const unsigned a[4], const unsigned b[2]) {
    asm volatile(
        "mma.sync.aligned.m16n8k8.row.col.f32.tf32.tf32.f32 "
        "{%0,%1,%2,%3}, {%4,%5,%6,%7}, {%8,%9}, {%0,%1,%2,%3};"
        : "+f"(c[0]), "+f"(c[1]), "+f"(c[2]), "+f"(c[3])
        : "r"(a[0]), "r"(a[1]), "r"(a[2]), "r"(a[3]), "r"(b[0]), "r"(b[1]));
}

// Global barrier: 128 CTAs, 1/SM, all co-resident.
__device__ __forceinline__ void gbar(unsigned target) {
    __syncthreads();
    if (threadIdx.x == 0) {
        __threadfence();
        unsigned t = atomicAdd(&g_count, 1);
        if (t == NCTA - 1) {
            atomicExch(&g_count, 0);
            __threadfence();
            g_gen = target;
        } else {
            while ((int)(g_gen - target) < 0) {}
            __threadfence();
        }
    }
    __syncthreads();
}

// Stage one BK=32 chunk: A 128x32 fp32, B 32x128 fp32, pure cp.async 16B.
template <bool DUAL>
__device__ __forceinline__ void stage_chunk(
    float* As_, float* Bs_, int st, int cc,
    const float* A1, const float* A2,
    const float* W1, const float* W2,
    int m0, int n0, int tid)
{
    const bool ph = DUAL && (cc >= 16);
    const float* Ap = ph ? A2 : A1;
    const float* Wp = ph ? W2 : W1;
    const int kc = (cc & 15) * 32;

    const int ar = tid >> 1;                 // 0..127
    const int ks = (tid & 1) * 16;           // 0 or 16
    float*       ad = As_ + (st * 128 + ar) * APITCH + ks;
    const float* as = Ap + (m0 + ar) * Hn + kc + ks;
    cp16(ad,      as);
    cp16(ad + 4,  as + 4);
    cp16(ad + 8,  as + 8);
    cp16(ad + 12, as + 12);

    const int bk = tid >> 3;                 // 0..31
    const int cs = (tid & 7) * 16;           // 0..112
    float*       bd = Bs_ + (st * 32 + bk) * BPITCH + cs;
    const float* bs = Wp + (kc + bk) * Hn + n0 + cs;
    cp16(bd,      bs);
    cp16(bd + 4,  bs + 4);
    cp16(bd + 8,  bs + 8);
    cp16(bd + 12, bs + 12);
}

// One 128x128 job: C = elu(A1@W1 [+ A2@W2] + bias [+ Win0 one-hot row]).
// tf32 MMA, fp32 accumulate. State written tf32-rounded; hist full fp32.
template <bool DUAL, bool LAYER0, bool STORE>
__device__ __forceinline__ void do_job(
    float* As_, float* Bs_, int t,
    const float* A1, const float* A2,
    const float* W1, const float* W2,
    const float* bias, const int* x, const float* Win0,
    float* Cout, int m0, int n0)
{
    const int tid  = threadIdx.x;
    const int warp = tid >> 5, lane = tid & 31;
    const int mw = warp & 1;            // 2 warps along m (64 rows each)
    const int nw = warp >> 1;           // 4 warps along n (32 cols each)
    const int quad = lane >> 2, qt = lane & 3;

    float acc[4][4][4];
#pragma unroll
    for (int a = 0; a < 4; a++)
#pragma unroll
        for (int b = 0; b < 4; b++)
#pragma unroll
            for (int v = 0; v < 4; v++) acc[a][b][v] = 0.f;

    const int NCH = DUAL ? 32 : 16;
    stage_chunk<DUAL>(As_, Bs_, 0, 0, A1, A2, W1, W2, m0, n0, tid);
    cp_commit();

    for (int cc = 0; cc < NCH; cc++) {
        cp_wait0();
        __syncthreads();
        const int st = cc & 1;
        if (cc + 1 < NCH)
            stage_chunk<DUAL>(As_, Bs_, st ^ 1, cc + 1, A1, A2, W1, W2, m0, n0, tid);
        cp_commit();

        const float* Ab = As_ + st * 128 * APITCH;
        const float* Bb = Bs_ + st * 32 * BPITCH;
#pragma unroll
        for (int k8 = 0; k8 < 32; k8 += 8) {
            unsigned af[4][4], bf[4][2];
#pragma unroll
            for (int ma = 0; ma < 4; ma++) {
                const int r = mw * 64 + ma * 16;
                af[ma][0] = __float_as_uint(Ab[(r + quad)     * APITCH + k8 + qt]);
                af[ma][1] = __float_as_uint(Ab[(r + quad + 8) * APITCH + k8 + qt]);
                af[ma][2] = __float_as_uint(Ab[(r + quad)     * APITCH + k8 + qt + 4]);
                af[ma][3] = __float_as_uint(Ab[(r + quad + 8) * APITCH + k8 + qt + 4]);
            }
#pragma unroll
            for (int na = 0; na < 4; na++) {
                const int c = nw * 32 + na * 8 + quad;
                bf[na][0] = __float_as_uint(Bb[(k8 + qt)     * BPITCH + c]);
                bf[na][1] = __float_as_uint(Bb[(k8 + qt + 4) * BPITCH + c]);
            }
#pragma unroll
            for (int ma = 0; ma < 4; ma++)
#pragma unroll
                for (int na = 0; na < 4; na++)
                    mma8(acc[ma][na], af[ma], bf[na]);
        }
        __syncthreads();
    }

    // epilogue: + bias (+ Win0[x[t-1]] row for layer 0), ELU, store.
#pragma unroll
    for (int ma = 0; ma < 4; ma++) {
        const int r0 = m0 + mw * 64 + ma * 16 + quad;
        const int r1 = r0 + 8;
        int idx0 = 0, idx1 = 0;
        const bool l0add = LAYER0 && (t > 0);
        if (l0add) {
            idx0 = x[r0 * Ln + (t - 1)];
            idx1 = x[r1 * Ln + (t - 1)];
        }
#pragma unroll
        for (int nb = 0; nb < 4; nb++) {
            const int col = n0 + nw * 32 + nb * 8 + 2 * qt;
            const float2 bv = *reinterpret_cast<const float2*>(&bias[col]);
            float2 w0 = make_float2(0.f, 0.f), w1 = make_float2(0.f, 0.f);
            if (l0add) {
                w0 = *reinterpret_cast<const float2*>(&Win0[idx0 * Hn + col]);
                w1 = *reinterpret_cast<const float2*>(&Win0[idx1 * Hn + col]);
            }
            float v0 = acc[ma][nb][0] + bv.x + w0.x;
            float v1 = acc[ma][nb][1] + bv.y + w0.y;
            float v2 = acc[ma][nb][2] + bv.x + w1.x;
            float v3 = acc[ma][nb][3] + bv.y + w1.y;
            v0 = (v0 > 0.f) ? v0 : expm1f(v0);
            v1 = (v1 > 0.f) ? v1 : expm1f(v1);
            v2 = (v2 > 0.f) ? v2 : expm1f(v2);
            v3 = (v3 > 0.f) ? v3 : expm1f(v3);
            // state: tf32-rounded (next GEMM consumes as tf32, cp.async verbatim)
            *reinterpret_cast<float2*>(&Cout[r0 * Hn + col]) = make_float2(tf32r(v0), tf32r(v1));
            *reinterpret_cast<float2*>(&Cout[r1 * Hn + col]) = make_float2(tf32r(v2), tf32r(v3));
            if (STORE) {
                *reinterpret_cast<float2*>(&g_hist[t][r0][col]) = make_float2(v0, v1);
                *reinterpret_cast<float2*>(&g_hist[t][r1][col]) = make_float2(v2, v3);
            }
        }
    }
}

// ---------------------------------------------------------------------------
__global__ void __launch_bounds__(NTHREADS, 1) rnn_persistent(
    const int*   __restrict__ x,         // [B][L]
    const float* __restrict__ Win0,      // [2][H]
    const float* __restrict__ Win_rest,  // [3][H][H]
    const float* __restrict__ Wc,        // [4][H][H]
    const float* __restrict__ bc)        // [4][H]
{
    extern __shared__ __align__(16) float dsm[];
    float* As_ = dsm;
    float* Bs_ = dsm + A_WORDS;

    const int tid  = threadIdx.x;
    const int cta  = blockIdx.x;
    const int gtid = cta * NTHREADS + tid;

    unsigned base = g_gen;               // stable until first barrier releases
    unsigned bar  = 0;

    // --- prologue: tf32-round weights into g_W, zero initial state ---------
    {
        const float4* wc4 = reinterpret_cast<const float4*>(Wc);
        float4* d = reinterpret_cast<float4*>(&g_W[0][0][0]);
        for (int i = gtid; i < 4 * Hn * Hn / 4; i += NCTA * NTHREADS) {
            float4 v = wc4[i];
            d[i] = make_float4(tf32r(v.x), tf32r(v.y), tf32r(v.z), tf32r(v.w));
        }
        const float4* wr4 = reinterpret_cast<const float4*>(Win_rest);
        float4* d2 = reinterpret_cast<float4*>(&g_W[4][0][0]);
        for (int i = gtid; i < 3 * Hn * Hn / 4; i += NCTA * NTHREADS) {
            float4 v = wr4[i];
            d2[i] = make_float4(tf32r(v.x), tf32r(v.y), tf32r(v.z), tf32r(v.w));
        }
        float4* z = reinterpret_cast<float4*>(&g_S[0][0][0][0]);
        const float4 z4 = make_float4(0.f, 0.f, 0.f, 0.f);
        for (int i = gtid; i < 4 * Bn * Hn / 4; i += NCTA * NTHREADS)
            z[i] = z4;
    }
    gbar(base + (++bar));

    // --- wavefront: phase w runs layers j with t = w - j --------------------
    const int slot = cta >> 5;              // 0..3 active-layer slot
    const int tile = cta & 31;              // 32 tiles of 128x128
    const int m0 = (tile >> 2) * 128;       // 8 m-tiles
    const int n0 = (tile & 3) * 128;        // 4 n-tiles

    for (int w = 0; w < Ln + 3; w++) {
        const int jhi = (w < 3) ? w : 3;
        const int jlo = (w > Ln - 1) ? (w - (Ln - 1)) : 0;
        const int nact = jhi - jlo + 1;
        if (slot < nact) {
            const int j = jhi - slot;
            const int t = w - j;
            const int pin = t & 1, pout = pin ^ 1;
            const float* A1 = &g_S[pin][j][0][0];
            const float* A2 = (j > 0) ? &g_S[pout][j - 1][0][0] : A1;
            const float* W1 = &g_W[j][0][0];
            const float* W2 = (j > 0) ? &g_W[4 + j - 1][0][0] : W1;
            const float* bias = bc + j * Hn;
            float* Cout = &g_S[pout][j][0][0];
            switch (j) {
                case 0:
                    do_job<false, true, false>(As_, Bs_, t, A1, A2, W1, W2, bias, x, Win0, Cout, m0, n0);
                    break;
                case 3:
                    do_job<true, false, true>(As_, Bs_, t, A1, A2, W1, W2, bias, x, Win0, Cout, m0, n0);
                    break;
                default:
                    do_job<true, false, false>(As_, Bs_, t, A1, A2, W1, W2, bias, x, Win0, Cout, m0, n0);
                    break;
            }
        }
        gbar(base + (++bar));
    }
}

// ---------------------------------------------------------------------------
// Final pass: one warp per batch row (verified in rounds 2-3, fp32 hist).
// ---------------------------------------------------------------------------
__global__ void logp_kernel(const float* __restrict__ Wout,  // [H][2]
                            const float* __restrict__ bout,  // [2]
                            const int*   __restrict__ xsym,  // [B][L]
                            float* __restrict__ out)         // [B]
{
    const int gw   = (blockIdx.x * blockDim.x + threadIdx.x) >> 5;
    const int lane = threadIdx.x & 31;
    if (gw >= Bn) return;
    const int b = gw;

    float w0[16], w1[16];
#pragma unroll
    for (int i = 0; i < 16; i++) {
        const int k = lane + 32 * i;
        w0[i] = Wout[k * 2 + 0];
        w1[i] = Wout[k * 2 + 1];
    }
    const float b0 = bout[0], b1 = bout[1];

    float acc = 0.f;
    for (int t = 0; t < Ln; t++) {
        const float* h = &g_hist[t][b][0];
        float s0 = 0.f, s1 = 0.f;
#pragma unroll
        for (int i = 0; i < 16; i++) {
            const float hv = h[lane + 32 * i];
            s0 += hv * w0[i];
            s1 += hv * w1[i];
        }
#pragma unroll
        for (int off = 16; off > 0; off >>= 1) {
            s0 += __shfl_xor_sync(0xffffffffu, s0, off);
            s1 += __shfl_xor_sync(0xffffffffu, s1, off);
        }
        s0 += b0; s1 += b1;
        const float m   = fmaxf(s0, s1);
        const float lse = m + logf(expf(s0 - m) + expf(s1 - m));
        const float sel = (xsym[b * Ln + t] == 0) ? s0 : s1;
        acc += sel - lse;
    }
    if (lane == 0) out[b] = 0.5f * acc;
}

// ---------------------------------------------------------------------------
extern "C" void kernel_launch(void* const* d_in, const int* in_sizes, int n_in,
                              void* d_out, int out_size) {
    (void)in_sizes; (void)n_in; (void)out_size;
    const int*   x        = (const int*)  d_in[0];  // [B, L]
    const float* Win0     = (const float*)d_in[1];  // [2, H]
    const float* Win_rest = (const float*)d_in[2];  // [3, H, H]
    const float* Wc       = (const float*)d_in[3];  // [4, H, H]
    const float* bc       = (const float*)d_in[4];  // [4, H]
    const float* Wout     = (const float*)d_in[5];  // [H, 2]
    const float* bout     = (const float*)d_in[6];  // [2]
    float* out = (float*)d_out;                     // [B]

    cudaFuncSetAttribute(rnn_persistent,
                         cudaFuncAttributeMaxDynamicSharedMemorySize, SMEM_BYTES);

    rnn_persistent<<<NCTA, NTHREADS, SMEM_BYTES>>>(x, Win0, Win_rest, Wc, bc);
    logp_kernel<<<Bn / 8, 256>>>(Wout, bout, x, out);
}

// round 7
// speedup vs baseline: 5.7863x; 2.0071x over previous
#include <cuda_runtime.h>
#include <cuda_fp16.h>
#include <math.h>

#define Bn 1024
#define Ln 64
#define Hn 512
#define NCTA 128
#define NTHREADS 256

// fp16 ping-pong state + fp16 weights (converted once/launch), fp32 history.
__device__ __half g_S16[2][4][Bn][Hn];   // 8 MB
__device__ __half g_W16[7][Hn][Hn];      // [0..3]=Wc, [4..6]=Win_rest, [k][n] layout
__device__ float  g_hist[Ln][Bn][Hn];    // 128 MB layer-3 outputs (full fp32)
__device__ unsigned g_count;
__device__ volatile unsigned g_gen;

struct Smem {
    __half A[2][128][40];   // 128x32 tile, pitch 40 half = 80B (LDSM conflict-free)
    __half B[2][32][136];   // 32x128 tile, pitch 136 half = 272B
};                          // 37888 B static

// ---------------------------------------------------------------------------
__device__ __forceinline__ void cp16(void* dst, const void* src) {
    unsigned d = (unsigned)__cvta_generic_to_shared(dst);
    asm volatile("cp.async.cg.shared.global [%0], [%1], 16;" :: "r"(d), "l"(src));
}
__device__ __forceinline__ void cp_commit() {
    asm volatile("cp.async.commit_group;" ::: "memory");
}
__device__ __forceinline__ void cp_wait0() {
    asm volatile("cp.async.wait_group 0;" ::: "memory");
}
__device__ __forceinline__ void ldsm4(unsigned r[4], const void* p) {
    unsigned a = (unsigned)__cvta_generic_to_shared(p);
    asm volatile("ldmatrix.sync.aligned.m8n8.x4.shared.b16 {%0,%1,%2,%3}, [%4];"
                 : "=r"(r[0]), "=r"(r[1]), "=r"(r[2]), "=r"(r[3]) : "r"(a));
}
__device__ __forceinline__ void ldsm4t(unsigned r[4], const void* p) {
    unsigned a = (unsigned)__cvta_generic_to_shared(p);
    asm volatile("ldmatrix.sync.aligned.m8n8.x4.trans.shared.b16 {%0,%1,%2,%3}, [%4];"
                 : "=r"(r[0]), "=r"(r[1]), "=r"(r[2]), "=r"(r[3]) : "r"(a));
}
__device__ __forceinline__ void mma_f16(float c[4], const unsigned a[4],
                                        unsigned b0, unsigned b1) {
    asm volatile(
        "mma.sync.aligned.m16n8k16.row.col.f32.f16.f16.f32 "
        "{%0,%1,%2,%3}, {%4,%5,%6,%7}, {%8,%9}, {%0,%1,%2,%3};"
        : "+f"(c[0]), "+f"(c[1]), "+f"(c[2]), "+f"(c[3])
        : "r"(a[0]), "r"(a[1]), "r"(a[2]), "r"(a[3]), "r"(b0), "r"(b1));
}

// Global barrier: 128 CTAs, 1/SM, all co-resident (verified rounds 3-5).
__device__ __forceinline__ void gbar(unsigned target) {
    __syncthreads();
    if (threadIdx.x == 0) {
        __threadfence();
        unsigned t = atomicAdd(&g_count, 1);
        if (t == NCTA - 1) {
            atomicExch(&g_count, 0);
            __threadfence();
            g_gen = target;
        } else {
            while ((int)(g_gen - target) < 0) {}
            __threadfence();
        }
    }
    __syncthreads();
}

// Stage one BK=32 chunk (A: 128x32 half = 64B/row, B: 32x128 half = 256B/row).
// FIXED vs round 4: B rows now fully staged (each of 8 threads copies 32B).
template <bool DUAL>
__device__ __forceinline__ void stage_chunk(
    Smem* sm, int st, int cc,
    const __half* A1, const __half* A2,
    const __half* W1, const __half* W2,
    int m0, int n0, int tid)
{
    const bool ph = DUAL && (cc >= 16);
    const __half* As = ph ? A2 : A1;
    const __half* Ws = ph ? W2 : W1;
    const int kc = (cc & 15) * 32;

    const int ar  = tid >> 1;              // 0..127
    const int asg = (tid & 1) * 16;        // halfs 0 or 16
    cp16(&sm->A[st][ar][asg],     As + (m0 + ar) * Hn + kc + asg);
    cp16(&sm->A[st][ar][asg + 8], As + (m0 + ar) * Hn + kc + asg + 8);

    const int br = tid >> 3;               // 0..31
    const int bs = (tid & 7) * 16;         // halfs 0..112 (32B per thread)
    cp16(&sm->B[st][br][bs],     Ws + (kc + br) * Hn + n0 + bs);
    cp16(&sm->B[st][br][bs + 8], Ws + (kc + br) * Hn + n0 + bs + 8);
}

// One 128x128 job: C = elu(A1@W1 [+ A2@W2] + bias [+ Win0 one-hot row]).
// fp16 in / fp32 accumulate; state stored fp16, hist stored fp32.
template <bool DUAL, bool LAYER0, bool STORE>
__device__ __forceinline__ void do_job(
    Smem* sm, int t,
    const __half* A1, const __half* A2,
    const __half* W1, const __half* W2,
    const float* bias, const int* x, const float* Win0,
    __half* Cout, int m0, int n0)
{
    const int tid  = threadIdx.x;
    const int warp = tid >> 5, lane = tid & 31;
    const int mw = warp & 1;           // 2 warps along m (64 rows each)
    const int nw = warp >> 1;          // 4 warps along n (32 cols each)
    const int quad = lane >> 2, qt = lane & 3;
    const int lrow = lane & 15, lhi = (lane >> 4) << 3;

    float acc[4][4][4];
#pragma unroll
    for (int a = 0; a < 4; a++)
#pragma unroll
        for (int b = 0; b < 4; b++)
#pragma unroll
            for (int v = 0; v < 4; v++) acc[a][b][v] = 0.f;

    const int NCH = DUAL ? 32 : 16;
    stage_chunk<DUAL>(sm, 0, 0, A1, A2, W1, W2, m0, n0, tid);
    cp_commit();

    for (int cc = 0; cc < NCH; cc++) {
        cp_wait0();
        __syncthreads();
        const int st = cc & 1;
        if (cc + 1 < NCH)
            stage_chunk<DUAL>(sm, st ^ 1, cc + 1, A1, A2, W1, W2, m0, n0, tid);
        cp_commit();

#pragma unroll
        for (int k16 = 0; k16 < 32; k16 += 16) {
            unsigned a[4][4];
#pragma unroll
            for (int ma = 0; ma < 4; ma++)
                ldsm4(a[ma], &sm->A[st][mw * 64 + ma * 16 + lrow][k16 + lhi]);
            unsigned b0[4], b1[4];
            ldsm4t(b0, &sm->B[st][k16 + lrow][nw * 32 + lhi]);
            ldsm4t(b1, &sm->B[st][k16 + lrow][nw * 32 + 16 + lhi]);
#pragma unroll
            for (int ma = 0; ma < 4; ma++) {
                mma_f16(acc[ma][0], a[ma], b0[0], b0[1]);
                mma_f16(acc[ma][1], a[ma], b0[2], b0[3]);
                mma_f16(acc[ma][2], a[ma], b1[0], b1[1]);
                mma_f16(acc[ma][3], a[ma], b1[2], b1[3]);
            }
        }
    }

    // epilogue: + bias (+ Win0[x[t-1]] row for layer 0), ELU, store
#pragma unroll
    for (int ma = 0; ma < 4; ma++) {
        const int r0 = m0 + mw * 64 + ma * 16 + quad;
        const int r1 = r0 + 8;
        int idx0 = 0, idx1 = 0;
        const bool l0add = LAYER0 && (t > 0);
        if (l0add) {
            idx0 = x[r0 * Ln + (t - 1)];
            idx1 = x[r1 * Ln + (t - 1)];
        }
#pragma unroll
        for (int nb = 0; nb < 4; nb++) {
            const int col = n0 + nw * 32 + nb * 8 + 2 * qt;
            const float2 bv = *reinterpret_cast<const float2*>(&bias[col]);
            float2 w0 = make_float2(0.f, 0.f), w1 = make_float2(0.f, 0.f);
            if (l0add) {
                w0 = *reinterpret_cast<const float2*>(&Win0[idx0 * Hn + col]);
                w1 = *reinterpret_cast<const float2*>(&Win0[idx1 * Hn + col]);
            }
            float v0 = acc[ma][nb][0] + bv.x + w0.x;
            float v1 = acc[ma][nb][1] + bv.y + w0.y;
            float v2 = acc[ma][nb][2] + bv.x + w1.x;
            float v3 = acc[ma][nb][3] + bv.y + w1.y;
            v0 = (v0 > 0.f) ? v0 : expm1f(v0);
            v1 = (v1 > 0.f) ? v1 : expm1f(v1);
            v2 = (v2 > 0.f) ? v2 : expm1f(v2);
            v3 = (v3 > 0.f) ? v3 : expm1f(v3);
            // state: fp16-rounded carry (same mantissa as tf32; proven-safe eps)
            *reinterpret_cast<__half2*>(&Cout[r0 * Hn + col]) = __floats2half2_rn(v0, v1);
            *reinterpret_cast<__half2*>(&Cout[r1 * Hn + col]) = __floats2half2_rn(v2, v3);
            if (STORE) {
                // history: full fp32 (exact logp path from rounds 2/3/5)
                *reinterpret_cast<float2*>(&g_hist[t][r0][col]) = make_float2(v0, v1);
                *reinterpret_cast<float2*>(&g_hist[t][r1][col]) = make_float2(v2, v3);
            }
        }
    }
}

// ---------------------------------------------------------------------------
__global__ void __launch_bounds__(NTHREADS, 1) rnn_persistent(
    const int*   __restrict__ x,         // [B][L]
    const float* __restrict__ Win0,      // [2][H]
    const float* __restrict__ Win_rest,  // [3][H][H]
    const float* __restrict__ Wc,        // [4][H][H]
    const float* __restrict__ bc)        // [4][H]
{
    __shared__ __align__(16) Smem sm;

    const int tid  = threadIdx.x;
    const int cta  = blockIdx.x;
    const int gtid = cta * NTHREADS + tid;

    unsigned base = g_gen;               // stable until first barrier releases
    unsigned bar  = 0;

    // --- prologue: convert weights to fp16, zero initial state -------------
    {
        const float4* wc4 = reinterpret_cast<const float4*>(Wc);
        __half2* d = reinterpret_cast<__half2*>(&g_W16[0][0][0]);
        for (int i = gtid; i < 4 * Hn * Hn / 4; i += NCTA * NTHREADS) {
            float4 v = wc4[i];
            d[2 * i]     = __floats2half2_rn(v.x, v.y);
            d[2 * i + 1] = __floats2half2_rn(v.z, v.w);
        }
        const float4* wr4 = reinterpret_cast<const float4*>(Win_rest);
        __half2* d2 = reinterpret_cast<__half2*>(&g_W16[4][0][0]);
        for (int i = gtid; i < 3 * Hn * Hn / 4; i += NCTA * NTHREADS) {
            float4 v = wr4[i];
            d2[2 * i]     = __floats2half2_rn(v.x, v.y);
            d2[2 * i + 1] = __floats2half2_rn(v.z, v.w);
        }
        uint4* z = reinterpret_cast<uint4*>(&g_S16[0][0][0][0]);
        const uint4 z4 = make_uint4(0u, 0u, 0u, 0u);
        for (int i = gtid; i < 4 * Bn * Hn * 2 / 16; i += NCTA * NTHREADS)
            z[i] = z4;
    }
    gbar(base + (++bar));

    // --- wavefront schedule: phase w runs layers j with t = w - j ----------
    const int slot = cta >> 5;             // 0..3: which active layer
    const int tile = cta & 31;             // 32 tiles of 128x128
    const int m0 = (tile >> 2) * 128;
    const int n0 = (tile & 3) * 128;

    for (int w = 0; w < Ln + 3; w++) {
        const int jhi = (w < 3) ? w : 3;
        const int jlo = (w > Ln - 1) ? (w - (Ln - 1)) : 0;
        const int nact = jhi - jlo + 1;
        if (slot < nact) {
            const int j = jhi - slot;
            const int t = w - j;
            const int pin = t & 1, pout = pin ^ 1;
            const __half* A1 = &g_S16[pin][j][0][0];
            const __half* A2 = (j > 0) ? &g_S16[pout][j - 1][0][0] : A1;
            const __half* W1 = &g_W16[j][0][0];
            const __half* W2 = (j > 0) ? &g_W16[4 + j - 1][0][0] : W1;
            const float* bias = bc + j * Hn;
            __half* Cout = &g_S16[pout][j][0][0];
            switch (j) {
                case 0:
                    do_job<false, true, false>(&sm, t, A1, A2, W1, W2, bias, x, Win0, Cout, m0, n0);
                    break;
                case 3:
                    do_job<true, false, true>(&sm, t, A1, A2, W1, W2, bias, x, Win0, Cout, m0, n0);
                    break;
                default:
                    do_job<true, false, false>(&sm, t, A1, A2, W1, W2, bias, x, Win0, Cout, m0, n0);
                    break;
            }
        }
        gbar(base + (++bar));
    }
}

// ---------------------------------------------------------------------------
// Final pass: one warp per batch row, fp32 hist (verified rounds 2/3/5).
// ---------------------------------------------------------------------------
__global__ void logp_kernel(const float* __restrict__ Wout,  // [H][2]
                            const float* __restrict__ bout,  // [2]
                            const int*   __restrict__ xsym,  // [B][L]
                            float* __restrict__ out)         // [B]
{
    const int gw   = (blockIdx.x * blockDim.x + threadIdx.x) >> 5;
    const int lane = threadIdx.x & 31;
    if (gw >= Bn) return;
    const int b = gw;

    float w0[16], w1[16];
#pragma unroll
    for (int i = 0; i < 16; i++) {
        const int k = lane + 32 * i;
        w0[i] = Wout[k * 2 + 0];
        w1[i] = Wout[k * 2 + 1];
    }
    const float b0 = bout[0], b1 = bout[1];

    float acc = 0.f;
    for (int t = 0; t < Ln; t++) {
        const float* h = &g_hist[t][b][0];
        float s0 = 0.f, s1 = 0.f;
#pragma unroll
        for (int i = 0; i < 16; i++) {
            const float hv = h[lane + 32 * i];
            s0 += hv * w0[i];
            s1 += hv * w1[i];
        }
#pragma unroll
        for (int off = 16; off > 0; off >>= 1) {
            s0 += __shfl_xor_sync(0xffffffffu, s0, off);
            s1 += __shfl_xor_sync(0xffffffffu, s1, off);
        }
        s0 += b0; s1 += b1;
        const float m   = fmaxf(s0, s1);
        const float lse = m + logf(expf(s0 - m) + expf(s1 - m));
        const float sel = (xsym[b * Ln + t] == 0) ? s0 : s1;
        acc += sel - lse;
    }
    if (lane == 0) out[b] = 0.5f * acc;
}

// ---------------------------------------------------------------------------
extern "C" void kernel_launch(void* const* d_in, const int* in_sizes, int n_in,
                              void* d_out, int out_size) {
    (void)in_sizes; (void)n_in; (void)out_size;
    const int*   x        = (const int*)  d_in[0];  // [B, L]
    const float* Win0     = (const float*)d_in[1];  // [2, H]
    const float* Win_rest = (const float*)d_in[2];  // [3, H, H]
    const float* Wc       = (const float*)d_in[3];  // [4, H, H]
    const float* bc       = (const float*)d_in[4];  // [4, H]
    const float* Wout     = (const float*)d_in[5];  // [H, 2]
    const float* bout     = (const float*)d_in[6];  // [2]
    float* out = (float*)d_out;                     // [B]

    rnn_persistent<<<NCTA, NTHREADS>>>(x, Win0, Win_rest, Wc, bc);
    logp_kernel<<<Bn / 8, 256>>>(Wout, bout, x, out);
}

// round 8
// speedup vs baseline: 6.3549x; 1.0983x over previous
#include <cuda_runtime.h>
#include <cuda_fp16.h>
#include <math.h>

#define Bn 1024
#define Ln 64
#define Hn 512
#define NCTA 256
#define NTHREADS 256

// fp16 ping-pong state + fp16 weights (converted once/launch), fp16 history.
__device__ __half g_S16[2][4][Bn][Hn];   // 8 MB
__device__ __half g_W16[7][Hn][Hn];      // [0..3]=Wc, [4..6]=Win_rest, [k][n] layout
__device__ __half g_h16[Ln][Bn][Hn];     // 64 MB layer-3 outputs
__device__ float  g_lp[8][Bn];           // per-t-chunk partial log-probs
__device__ unsigned g_count;
__device__ volatile unsigned g_gen;

struct Smem {
    __half A[2][128][40];   // 128x32 tile, pitch 80B (LDSM conflict-free)
    __half B[2][32][72];    // 32x64 tile,  pitch 144B (LDSM conflict-free)
};                          // 29696 B static -> 2 CTAs/SM fits easily

// ---------------------------------------------------------------------------
__device__ __forceinline__ void cp16(void* dst, const void* src) {
    unsigned d = (unsigned)__cvta_generic_to_shared(dst);
    asm volatile("cp.async.cg.shared.global [%0], [%1], 16;" :: "r"(d), "l"(src));
}
__device__ __forceinline__ void cp_commit() {
    asm volatile("cp.async.commit_group;" ::: "memory");
}
__device__ __forceinline__ void cp_wait0() {
    asm volatile("cp.async.wait_group 0;" ::: "memory");
}
__device__ __forceinline__ void ldsm4(unsigned r[4], const void* p) {
    unsigned a = (unsigned)__cvta_generic_to_shared(p);
    asm volatile("ldmatrix.sync.aligned.m8n8.x4.shared.b16 {%0,%1,%2,%3}, [%4];"
                 : "=r"(r[0]), "=r"(r[1]), "=r"(r[2]), "=r"(r[3]) : "r"(a));
}
__device__ __forceinline__ void ldsm4t(unsigned r[4], const void* p) {
    unsigned a = (unsigned)__cvta_generic_to_shared(p);
    asm volatile("ldmatrix.sync.aligned.m8n8.x4.trans.shared.b16 {%0,%1,%2,%3}, [%4];"
                 : "=r"(r[0]), "=r"(r[1]), "=r"(r[2]), "=r"(r[3]) : "r"(a));
}
__device__ __forceinline__ void mma_f16(float c[4], const unsigned a[4],
                                        unsigned b0, unsigned b1) {
    asm volatile(
        "mma.sync.aligned.m16n8k16.row.col.f32.f16.f16.f32 "
        "{%0,%1,%2,%3}, {%4,%5,%6,%7}, {%8,%9}, {%0,%1,%2,%3};"
        : "+f"(c[0]), "+f"(c[1]), "+f"(c[2]), "+f"(c[3])
        : "r"(a[0]), "r"(a[1]), "r"(a[2]), "r"(a[3]), "r"(b0), "r"(b1));
}

// Global barrier: 256 CTAs, 2/SM via launch_bounds, all co-resident in wave 1.
__device__ __forceinline__ void gbar(unsigned target) {
    __syncthreads();
    if (threadIdx.x == 0) {
        __threadfence();
        unsigned t = atomicAdd(&g_count, 1);
        if (t == NCTA - 1) {
            atomicExch(&g_count, 0);
            __threadfence();
            g_gen = target;
        } else {
            while ((int)(g_gen - target) < 0) {}
            __threadfence();
        }
    }
    __syncthreads();
}

// Stage one BK=32 chunk (A: 128x32 = 64B/row, B: 32x64 = 128B/row). 3 cp16/thread.
template <bool DUAL>
__device__ __forceinline__ void stage_chunk(
    Smem* sm, int st, int cc,
    const __half* A1, const __half* A2,
    const __half* W1, const __half* W2,
    int m0, int n0, int tid)
{
    const bool ph = DUAL && (cc >= 16);
    const __half* As = ph ? A2 : A1;
    const __half* Ws = ph ? W2 : W1;
    const int kc = (cc & 15) * 32;

    const int ar  = tid >> 1;              // 0..127
    const int asg = (tid & 1) * 16;        // halfs 0 or 16
    cp16(&sm->A[st][ar][asg],     As + (m0 + ar) * Hn + kc + asg);
    cp16(&sm->A[st][ar][asg + 8], As + (m0 + ar) * Hn + kc + asg + 8);

    const int br = tid >> 3;               // 0..31
    const int bs = (tid & 7) * 8;          // halfs 0..56
    cp16(&sm->B[st][br][bs], Ws + (kc + br) * Hn + n0 + bs);
}

// One 128x64 job: C = elu(A1@W1 [+ A2@W2] + bias [+ Win0 one-hot row]).
// Warps: mw = warp>>1 (4 x 32 rows), nw = warp&1 (2 x 32 cols).
template <bool DUAL, bool LAYER0, bool STORE>
__device__ __forceinline__ void do_job(
    Smem* sm, int t,
    const __half* A1, const __half* A2,
    const __half* W1, const __half* W2,
    const float* bias, const int* x, const float* Win0,
    __half* Cout, int m0, int n0)
{
    const int tid  = threadIdx.x;
    const int warp = tid >> 5, lane = tid & 31;
    const int mw = warp >> 1;
    const int nw = warp & 1;
    const int quad = lane >> 2, qt = lane & 3;
    const int lrow = lane & 15, lhi = (lane >> 4) << 3;

    float acc[2][4][4];
#pragma unroll
    for (int a = 0; a < 2; a++)
#pragma unroll
        for (int b = 0; b < 4; b++)
#pragma unroll
            for (int v = 0; v < 4; v++) acc[a][b][v] = 0.f;

    const int NCH = DUAL ? 32 : 16;
    stage_chunk<DUAL>(sm, 0, 0, A1, A2, W1, W2, m0, n0, tid);
    cp_commit();

    for (int cc = 0; cc < NCH; cc++) {
        cp_wait0();
        __syncthreads();
        const int st = cc & 1;
        if (cc + 1 < NCH)
            stage_chunk<DUAL>(sm, st ^ 1, cc + 1, A1, A2, W1, W2, m0, n0, tid);
        cp_commit();

#pragma unroll
        for (int k16 = 0; k16 < 32; k16 += 16) {
            unsigned a[2][4];
            ldsm4(a[0], &sm->A[st][mw * 32 + lrow][k16 + lhi]);
            ldsm4(a[1], &sm->A[st][mw * 32 + 16 + lrow][k16 + lhi]);
            unsigned b0[4], b1[4];
            ldsm4t(b0, &sm->B[st][k16 + lrow][nw * 32 + lhi]);
            ldsm4t(b1, &sm->B[st][k16 + lrow][nw * 32 + 16 + lhi]);
#pragma unroll
            for (int ma = 0; ma < 2; ma++) {
                mma_f16(acc[ma][0], a[ma], b0[0], b0[1]);
                mma_f16(acc[ma][1], a[ma], b0[2], b0[3]);
                mma_f16(acc[ma][2], a[ma], b1[0], b1[1]);
                mma_f16(acc[ma][3], a[ma], b1[2], b1[3]);
            }
        }
    }

    // epilogue: + bias (+ Win0[x[t-1]] row for layer 0), ELU, store
#pragma unroll
    for (int ma = 0; ma < 2; ma++) {
        const int r0 = m0 + mw * 32 + ma * 16 + quad;
        const int r1 = r0 + 8;
        int idx0 = 0, idx1 = 0;
        const bool l0add = LAYER0 && (t > 0);
        if (l0add) {
            idx0 = x[r0 * Ln + (t - 1)];
            idx1 = x[r1 * Ln + (t - 1)];
        }
#pragma unroll
        for (int nb = 0; nb < 4; nb++) {
            const int col = n0 + nw * 32 + nb * 8 + 2 * qt;
            const float2 bv = *reinterpret_cast<const float2*>(&bias[col]);
            float2 w0 = make_float2(0.f, 0.f), w1 = make_float2(0.f, 0.f);
            if (l0add) {
                w0 = *reinterpret_cast<const float2*>(&Win0[idx0 * Hn + col]);
                w1 = *reinterpret_cast<const float2*>(&Win0[idx1 * Hn + col]);
            }
            float v0 = acc[ma][nb][0] + bv.x + w0.x;
            float v1 = acc[ma][nb][1] + bv.y + w0.y;
            float v2 = acc[ma][nb][2] + bv.x + w1.x;
            float v3 = acc[ma][nb][3] + bv.y + w1.y;
            v0 = (v0 > 0.f) ? v0 : expm1f(v0);
            v1 = (v1 > 0.f) ? v1 : expm1f(v1);
            v2 = (v2 > 0.f) ? v2 : expm1f(v2);
            v3 = (v3 > 0.f) ? v3 : expm1f(v3);
            const __half2 p01 = __floats2half2_rn(v0, v1);
            const __half2 p23 = __floats2half2_rn(v2, v3);
            *reinterpret_cast<__half2*>(&Cout[r0 * Hn + col]) = p01;
            *reinterpret_cast<__half2*>(&Cout[r1 * Hn + col]) = p23;
            if (STORE) {
                *reinterpret_cast<__half2*>(&g_h16[t][r0][col]) = p01;
                *reinterpret_cast<__half2*>(&g_h16[t][r1][col]) = p23;
            }
        }
    }
}

// ---------------------------------------------------------------------------
__global__ void __launch_bounds__(NTHREADS, 2) rnn_persistent(
    const int*   __restrict__ x,         // [B][L]
    const float* __restrict__ Win0,      // [2][H]
    const float* __restrict__ Win_rest,  // [3][H][H]
    const float* __restrict__ Wc,        // [4][H][H]
    const float* __restrict__ bc)        // [4][H]
{
    __shared__ __align__(16) Smem sm;

    const int tid  = threadIdx.x;
    const int cta  = blockIdx.x;
    const int gtid = cta * NTHREADS + tid;

    unsigned base = g_gen;               // stable until first barrier releases
    unsigned bar  = 0;

    // --- prologue: convert weights to fp16, zero initial state -------------
    {
        const float4* wc4 = reinterpret_cast<const float4*>(Wc);
        __half2* d = reinterpret_cast<__half2*>(&g_W16[0][0][0]);
        for (int i = gtid; i < 4 * Hn * Hn / 4; i += NCTA * NTHREADS) {
            float4 v = wc4[i];
            d[2 * i]     = __floats2half2_rn(v.x, v.y);
            d[2 * i + 1] = __floats2half2_rn(v.z, v.w);
        }
        const float4* wr4 = reinterpret_cast<const float4*>(Win_rest);
        __half2* d2 = reinterpret_cast<__half2*>(&g_W16[4][0][0]);
        for (int i = gtid; i < 3 * Hn * Hn / 4; i += NCTA * NTHREADS) {
            float4 v = wr4[i];
            d2[2 * i]     = __floats2half2_rn(v.x, v.y);
            d2[2 * i + 1] = __floats2half2_rn(v.z, v.w);
        }
        uint4* z = reinterpret_cast<uint4*>(&g_S16[0][0][0][0]);
        const uint4 z4 = make_uint4(0u, 0u, 0u, 0u);
        for (int i = gtid; i < 4 * Bn * Hn * 2 / 16; i += NCTA * NTHREADS)
            z[i] = z4;
    }
    gbar(base + (++bar));

    // --- wavefront: phase w runs layers j with t = w - j --------------------
    const int slot = cta >> 6;             // 0..3: active-layer slot
    const int tile = cta & 63;             // 64 tiles of 128x64
    const int m0 = (tile >> 3) * 128;      // 8 m-tiles
    const int n0 = (tile & 7) * 64;        // 8 n-tiles

    for (int w = 0; w < Ln + 3; w++) {
        const int jhi = (w < 3) ? w : 3;
        const int jlo = (w > Ln - 1) ? (w - (Ln - 1)) : 0;
        const int nact = jhi - jlo + 1;
        if (slot < nact) {
            const int j = jhi - slot;
            const int t = w - j;
            const int pin = t & 1, pout = pin ^ 1;
            const __half* A1 = &g_S16[pin][j][0][0];
            const __half* A2 = (j > 0) ? &g_S16[pout][j - 1][0][0] : A1;
            const __half* W1 = &g_W16[j][0][0];
            const __half* W2 = (j > 0) ? &g_W16[4 + j - 1][0][0] : W1;
            const float* bias = bc + j * Hn;
            __half* Cout = &g_S16[pout][j][0][0];
            switch (j) {
                case 0:
                    do_job<false, true, false>(&sm, t, A1, A2, W1, W2, bias, x, Win0, Cout, m0, n0);
                    break;
                case 3:
                    do_job<true, false, true>(&sm, t, A1, A2, W1, W2, bias, x, Win0, Cout, m0, n0);
                    break;
                default:
                    do_job<true, false, false>(&sm, t, A1, A2, W1, W2, bias, x, Win0, Cout, m0, n0);
                    break;
            }
        }
        gbar(base + (++bar));
    }
}

// ---------------------------------------------------------------------------
// Log-prob partials: warp (b, tc) handles 8 timesteps, writes g_lp[tc][b].
// ---------------------------------------------------------------------------
__global__ void logp_part(const float* __restrict__ Wout,  // [H][2]
                          const float* __restrict__ bout,  // [2]
                          const int*   __restrict__ xsym)  // [B][L]
{
    const int gw   = (blockIdx.x * blockDim.x + threadIdx.x) >> 5;
    const int lane = threadIdx.x & 31;
    const int b  = gw >> 3;
    const int tc = gw & 7;
    if (b >= Bn) return;

    float w0[16], w1[16];
#pragma unroll
    for (int i = 0; i < 8; i++) {
        const int k = lane * 2 + 64 * i;
        w0[2 * i]     = Wout[k * 2 + 0];
        w1[2 * i]     = Wout[k * 2 + 1];
        w0[2 * i + 1] = Wout[(k + 1) * 2 + 0];
        w1[2 * i + 1] = Wout[(k + 1) * 2 + 1];
    }
    const float b0 = bout[0], b1 = bout[1];

    float acc = 0.f;
#pragma unroll
    for (int tt = 0; tt < 8; tt++) {
        const int t = tc * 8 + tt;
        const __half* h = &g_h16[t][b][0];
        float s0 = 0.f, s1 = 0.f;
#pragma unroll
        for (int i = 0; i < 8; i++) {
            const __half2 hv = *reinterpret_cast<const __half2*>(&h[lane * 2 + 64 * i]);
            const float h0 = __half2float(hv.x);
            const float h1 = __half2float(hv.y);
            s0 += h0 * w0[2 * i] + h1 * w0[2 * i + 1];
            s1 += h0 * w1[2 * i] + h1 * w1[2 * i + 1];
        }
#pragma unroll
        for (int off = 16; off > 0; off >>= 1) {
            s0 += __shfl_xor_sync(0xffffffffu, s0, off);
            s1 += __shfl_xor_sync(0xffffffffu, s1, off);
        }
        s0 += b0; s1 += b1;
        const float m   = fmaxf(s0, s1);
        const float lse = m + logf(expf(s0 - m) + expf(s1 - m));
        const float sel = (xsym[b * Ln + t] == 0) ? s0 : s1;
        acc += sel - lse;
    }
    if (lane == 0) g_lp[tc][b] = acc;
}

// Deterministic final sum: out[b] = 0.5 * sum_tc g_lp[tc][b]
__global__ void logp_sum(float* __restrict__ out) {
    const int b = blockIdx.x * blockDim.x + threadIdx.x;
    if (b >= Bn) return;
    float s = 0.f;
#pragma unroll
    for (int tc = 0; tc < 8; tc++) s += g_lp[tc][b];
    out[b] = 0.5f * s;
}

// ---------------------------------------------------------------------------
extern "C" void kernel_launch(void* const* d_in, const int* in_sizes, int n_in,
                              void* d_out, int out_size) {
    (void)in_sizes; (void)n_in; (void)out_size;
    const int*   x        = (const int*)  d_in[0];  // [B, L]
    const float* Win0     = (const float*)d_in[1];  // [2, H]
    const float* Win_rest = (const float*)d_in[2];  // [3, H, H]
    const float* Wc       = (const float*)d_in[3];  // [4, H, H]
    const float* bc       = (const float*)d_in[4];  // [4, H]
    const float* Wout     = (const float*)d_in[5];  // [H, 2]
    const float* bout     = (const float*)d_in[6];  // [2]
    float* out = (float*)d_out;                     // [B]

    rnn_persistent<<<NCTA, NTHREADS>>>(x, Win0, Win_rest, Wc, bc);
    logp_part<<<(Bn * 8) / 8, 256>>>(Wout, bout, x);   // 1024 blocks, 8 warps each
    logp_sum<<<Bn / 256, 256>>>(out);
}